// round 7
// baseline (speedup 1.0000x reference)
#include <cuda_runtime.h>
#include <cuda_bf16.h>
#include <math.h>

#define NBINS   256
#define NCOPIES 8              // one sub-histogram per warp
#define THREADS 256
#define CTAS_PER_SM 4
#define BLOCKS  (148 * CTAS_PER_SM)   // 592
#define BATCH   5              // 11 full batches cover 99.35% of n4; tiny tail

__device__ unsigned int g_hist[NBINS];   // zero-initialized at module load
__device__ unsigned int g_ticket;        // zero-initialized at module load

__global__ __launch_bounds__(THREADS, CTAS_PER_SM)
void hist_kernel(const float* __restrict__ x, int n,
                 const void* __restrict__ bs_ptr, float* __restrict__ out) {
    __shared__ unsigned int sh[NCOPIES][NBINS];
    __shared__ unsigned int s_is_last;

    const int tid  = threadIdx.x;
    const int warp = tid >> 5;

    #pragma unroll
    for (int c = 0; c < NCOPIES; c++)
        sh[c][tid] = 0u;
    __syncthreads();

    unsigned int* myhist = sh[warp];
    const float scale = 1.00392156862745097e+00f;   // rn(256/255)

    const int n4 = n >> 2;
    const float4* __restrict__ x4 = (const float4*)x;
    const int stride = BLOCKS * THREADS;             // 151552
    const int gid = blockIdx.x * THREADS + tid;

    const int batch_span = BATCH * stride;
    const int n_full     = (n4 / batch_span) * batch_span;

    // main: unpredicated 5x LDG.128 batches (99.35% of data)
    for (int base = gid; base < n_full; base += batch_span) {
        float4 v[BATCH];
        #pragma unroll
        for (int u = 0; u < BATCH; u++)
            v[u] = x4[base + u * stride];
        #pragma unroll
        for (int u = 0; u < BATCH; u++) {
            #pragma unroll
            for (int k = 0; k < 4; k++) {
                float f = (k == 0) ? v[u].x : (k == 1) ? v[u].y
                        : (k == 2) ? v[u].z : v[u].w;
                int idx = (int)(f * scale);          // trunc==floor, f>=0
                idx = min(idx, NBINS - 1);           // memory safety
                atomicAdd(&myhist[idx], 1u);
            }
        }
    }

    // float4 tail: at most one iteration per thread (0.65% of data)
    for (int i = n_full + gid; i < n4; i += stride) {
        float4 v = x4[i];
        #pragma unroll
        for (int k = 0; k < 4; k++) {
            float f = (k == 0) ? v.x : (k == 1) ? v.y : (k == 2) ? v.z : v.w;
            int idx = (int)(f * scale);
            idx = min(idx, NBINS - 1);
            atomicAdd(&myhist[idx], 1u);
        }
    }

    // scalar tail (n % 4)
    for (int i = (n4 << 2) + gid; i < n; i += stride) {
        float f = x[i];
        int idx = (int)(f * scale);
        idx = min(idx, NBINS - 1);
        atomicAdd(&myhist[idx], 1u);
    }

    __syncthreads();

    // merge 8 warp copies -> one global atomic per bin per CTA
    unsigned int total = 0;
    #pragma unroll
    for (int c = 0; c < NCOPIES; c++)
        total += sh[c][tid];
    if (total) atomicAdd(&g_hist[tid], total);

    // ---- fused finalize: last CTA does the epilogue ----
    __threadfence();
    if (tid == 0)
        s_is_last = (atomicAdd(&g_ticket, 1u) == (unsigned)(BLOCKS - 1));
    __syncthreads();

    if (s_is_last) {
        __threadfence();                 // acquire: see all g_hist atomics
        unsigned int hv = g_hist[tid];
        unsigned int h0 = g_hist[0];

        // batchsize dtype sniff: int32 small value vs float32 bit pattern
        int iv = *(const int*)bs_ptr;
        float bs = (iv >= 0 && iv < (1 << 24)) ? (float)iv
                                               : *(const float*)bs_ptr;

        out[tid]         = (float)hv;
        out[NBINS + tid] = bs * (float)h0;

        __syncthreads();                 // all reads of g_hist done
        g_hist[tid] = 0u;                // reset for next graph replay
        if (tid == 0) g_ticket = 0u;
    }
}

extern "C" void kernel_launch(void* const* d_in, const int* in_sizes, int n_in,
                              void* d_out, int out_size) {
    int img_idx = 0, bs_idx = 1;
    if (n_in >= 2) {
        if (in_sizes[0] >= in_sizes[1]) { img_idx = 0; bs_idx = 1; }
        else                            { img_idx = 1; bs_idx = 0; }
    }
    const float* x = (const float*)d_in[img_idx];
    const void* bs = d_in[bs_idx];
    int n = in_sizes[img_idx];

    hist_kernel<<<BLOCKS, THREADS>>>(x, n, bs, (float*)d_out);
}